// round 12
// baseline (speedup 1.0000x reference)
#include <cuda_runtime.h>
#include <cuda_fp16.h>
#include <math.h>
#include <stdint.h>

#define HID 1024
#define G4  4096
#define NB  64
#define SQ  512
#define NA  128
#define MTOT (NB*SQ)

typedef __half half_t;

// ---------------- device globals (allocation-free rule) ----------------
__device__ float g_gx[(size_t)SQ*NB*G4];                  // [S][B][4H] fp32
__device__ half_t g_xe[(size_t)MTOT*HID];                 // activations: single fp16
__device__ half_t g_WiT_hi[(size_t)G4*HID];               // weights: fp16 hi/lo
__device__ half_t g_WiT_lo[(size_t)G4*HID];
__device__ half_t g_WhS_hi[(size_t)G4*HID];               // scan-permuted rows (hi used)
__device__ half_t g_WhS_lo[(size_t)G4*HID];
__device__ half_t g_WoT_hi[(size_t)NA*HID];
__device__ half_t g_WoT_lo[(size_t)NA*HID];
__device__ half_t g_hs[(size_t)MTOT*HID];                 // [b*SQ+s][j]
__device__ half_t g_h[2][NB*HID];
__device__ unsigned int g_cnt2[64];                       // per-group barrier counters

// ---------------- helpers ----------------
static __device__ __forceinline__ uint32_t smem_u32(const void* p){
    uint32_t a;
    asm("{ .reg .u64 t; cvta.to.shared.u64 t, %1; cvt.u32.u64 %0, t; }" : "=r"(a) : "l"(p));
    return a;
}
static __device__ __forceinline__ void ldsm4(uint32_t* r, uint32_t a){
    asm volatile("ldmatrix.sync.aligned.m8n8.x4.shared.b16 {%0,%1,%2,%3}, [%4];"
        : "=r"(r[0]),"=r"(r[1]),"=r"(r[2]),"=r"(r[3]) : "r"(a));
}
static __device__ __forceinline__ void mma_f16(float* d, const uint32_t* a, const uint32_t* b){
    asm volatile("mma.sync.aligned.m16n8k16.row.col.f32.f16.f16.f32 "
        "{%0,%1,%2,%3}, {%4,%5,%6,%7}, {%8,%9}, {%0,%1,%2,%3};"
        : "+f"(d[0]),"+f"(d[1]),"+f"(d[2]),"+f"(d[3])
        : "r"(a[0]),"r"(a[1]),"r"(a[2]),"r"(a[3]), "r"(b[0]),"r"(b[1]));
}
static __device__ __forceinline__ void cp16(uint32_t dst, const void* src){
    asm volatile("cp.async.cg.shared.global [%0], [%1], 16;" :: "r"(dst), "l"(src));
}
#define CP_COMMIT() asm volatile("cp.async.commit_group;" ::: "memory")
#define CP_WAIT(n)  asm volatile("cp.async.wait_group %0;" :: "n"(n) : "memory")

static __device__ __forceinline__ void split_f16(float v, half_t& hi, half_t& lo){
    hi = __float2half_rn(v);
    lo = __float2half_rn(v - __half2float(hi));
}
static __device__ __forceinline__ float fsigmoid(float x){
    return 1.f / (1.f + __expf(-x));
}
static __device__ __forceinline__ float ftanh(float x){
    return 1.f - 2.f / (__expf(2.f * x) + 1.f);
}

// ---------------- prep kernels ----------------
// Combined Wi+Wh transpose/split (z=0: Wi plain; z=1: Wh permuted).
// Blocks with z==0 && y==0 additionally zero h0; block (0,0,0) zeroes cnt.
__global__ void trans_WiWh(const float* __restrict__ Wi, const float* __restrict__ Wh){
    __shared__ float tile[32][33];
    const int z = blockIdx.z;
    const float* W = z ? Wh : Wi;
    int k0 = blockIdx.x * 32, n0 = blockIdx.y * 32;
    int tx = threadIdx.x, ty = threadIdx.y;     // 32 x 8
    int tid = ty * 32 + tx;

    if (z == 0 && blockIdx.y == 0){
        uint32_t* hz = (uint32_t*)g_h;          // 2*NB*HID halves = 65536 u32
        int nthr = 32 * 256;                    // 32 blocks in this stripe
        for (int p = blockIdx.x * 256 + tid; p < 65536; p += nthr) hz[p] = 0u;
        if (blockIdx.x == 0 && tid < 64) g_cnt2[tid] = 0u;
    }

    for (int i = ty; i < 32; i += 8)
        tile[i][tx] = W[(size_t)(k0 + i) * G4 + n0 + tx];
    __syncthreads();
    for (int i = ty; i < 32; i += 8){
        int n = n0 + i, k = k0 + tx;
        float v = tile[tx][i];
        half_t hi, lo; split_f16(v, hi, lo);
        if (z){
            int r = ((n & 1023) >> 4) * 64 + (n >> 10) * 16 + (n & 15);
            g_WhS_hi[(size_t)r * HID + k] = hi;
            g_WhS_lo[(size_t)r * HID + k] = lo;
        } else {
            g_WiT_hi[(size_t)n * HID + k] = hi;
            g_WiT_lo[(size_t)n * HID + k] = lo;
        }
    }
}

__global__ void gather_xe(const float* __restrict__ embed, const int* __restrict__ x){
    int r = blockIdx.x;                 // 0..32767, r = s*64 + b
    int s = r >> 6, b = r & 63;
    int tok = x[b * SQ + s];
    const float* src = embed + (size_t)tok * HID;
    for (int k = threadIdx.x; k < HID; k += blockDim.x)
        g_xe[(size_t)r * HID + k] = __float2half_rn(src[k]);
}

// Wo transpose/split + zero entire output buffer (dummy regions stay zero)
__global__ void trans_Wo_zero(const float* __restrict__ W, float* out, int out_n){
    __shared__ float tile[32][33];
    int k0 = blockIdx.x * 32, n0 = blockIdx.y * 32;
    int tx = threadIdx.x, ty = threadIdx.y;
    int tid = ty * 32 + tx;
    int nthr = gridDim.x * gridDim.y * 256;
    int bid = blockIdx.y * gridDim.x + blockIdx.x;
    for (int p = bid * 256 + tid; p < out_n; p += nthr) out[p] = 0.f;

    for (int i = ty; i < 32; i += 8)
        tile[i][tx] = W[(size_t)(k0 + i) * NA + n0 + tx];
    __syncthreads();
    for (int i = ty; i < 32; i += 8){
        int n = n0 + i, k = k0 + tx;
        half_t hi, lo; split_f16(tile[tx][i], hi, lo);
        g_WoT_hi[(size_t)n * HID + k] = hi;
        g_WoT_lo[(size_t)n * HID + k] = lo;
    }
}

// ---------------- 1-term fp16 GEMM: 128x128 tile (+optional bias) ----------------
#define X_AO   0
#define X_BO   18432
#define XBUF   36864
#define XSM_TOT (2*XBUF)

__global__ __launch_bounds__(256) void gemm_gx1(
    const half_t* __restrict__ A, const half_t* __restrict__ B,
    const float* __restrict__ bias, float* __restrict__ C, int ldc)
{
    extern __shared__ char sm[];
    const int tid = threadIdx.x, wid = tid >> 5, l = tid & 31;
    const int n0 = blockIdx.x * 128, m0 = blockIdx.y * 128;
    const int wm0 = (wid & 3) * 32, wn0 = (wid >> 2) * 64;

    uint32_t sbase = smem_u32(sm);

    uint32_t aA = sbase + X_AO + (uint32_t)(wm0 + (l & 15)) * 144 + (l >> 4) * 16;
    const int grp8 = l >> 3;
    const int n_off = (grp8 >> 1) * 8 + (l & 7);
    const int kblk = grp8 & 1;
    uint32_t aB = sbase + X_BO + (uint32_t)(wn0 + n_off) * 144 + kblk * 16;

    float d[2][8][4];
#pragma unroll
    for (int m = 0; m < 2; m++)
#pragma unroll
        for (int q = 0; q < 8; q++)
#pragma unroll
            for (int e = 0; e < 4; e++) d[m][q][e] = 0.f;

    auto issue = [&](int c, int buf){
        const int k0 = c * 64;
        uint32_t bb = sbase + buf * XBUF;
#pragma unroll
        for (int e = 0; e < 4; e++){
            int idx = tid + e * 256;
            int row = idx >> 3, q = idx & 7;
            cp16(bb + X_AO + row*144 + q*16, A + (size_t)(m0 + row)*HID + k0 + q*8);
            cp16(bb + X_BO + row*144 + q*16, B + (size_t)(n0 + row)*HID + k0 + q*8);
        }
    };

    issue(0, 0); CP_COMMIT();

    for (int c = 0; c < 16; c++){
        if (c < 15){ issue(c + 1, (c + 1) & 1); CP_COMMIT(); CP_WAIT(1); }
        else CP_WAIT(0);
        __syncthreads();
        const uint32_t bo = (uint32_t)(c & 1) * XBUF;
#pragma unroll
        for (int ks = 0; ks < 4; ks++){
            uint32_t ah[2][4];
            ldsm4(ah[0], aA + bo + ks*32);
            ldsm4(ah[1], aA + bo + 16*144 + ks*32);
            uint32_t bb4[4][4];
#pragma unroll
            for (int g = 0; g < 4; g++)
                ldsm4(bb4[g], aB + bo + g*2304 + ks*32);
#pragma unroll
            for (int m = 0; m < 2; m++)
#pragma unroll
                for (int g = 0; g < 4; g++)
#pragma unroll
                    for (int nn = 0; nn < 2; nn++)
                        mma_f16(d[m][g*2+nn], ah[m], bb4[g] + nn*2);
        }
        __syncthreads();
    }

#pragma unroll
    for (int m = 0; m < 2; m++)
#pragma unroll
        for (int q = 0; q < 8; q++){
            int row0 = m0 + wm0 + m*16 + (l >> 2);
            int col  = n0 + wn0 + q*8 + (l & 3)*2;
            float2 v0 = make_float2(d[m][q][0], d[m][q][1]);
            float2 v1 = make_float2(d[m][q][2], d[m][q][3]);
            if (bias){
                float b0 = bias[col], b1 = bias[col+1];
                v0.x += b0; v0.y += b1; v1.x += b0; v1.y += b1;
            }
            *(float2*)(C + (size_t)row0*ldc + col)     = v0;
            *(float2*)(C + (size_t)(row0+8)*ldc + col) = v1;
        }
}

// ---------------- persistent LSTM scan: K-split warps, Wh in registers ----------------
#define S_WH   0                 // 64 rows x 2064B = 132096 (one-time staging)
#define S_A    132096            // 32 rows x 2064B = 66048 (full K)
#define S_PT   198144            // 8 partials x 4224 = 33792
#define S_TOT  231936

__global__ __launch_bounds__(256, 1) void lstm_scan(const float* __restrict__ bh){
    extern __shared__ char sm[];
    const int tid = threadIdx.x, wid = tid >> 5, l = tid & 31;
    const int cta = blockIdx.x;
    const int grp = cta >> 6;          // batch group 0/1
    const int c   = cta & 63;          // column slice
    const int wn  = wid & 1;           // n-half (32 gate cols)
    const int kg  = wid >> 1;          // k-chunk (256)

    // stage Wh slice: rows c*64 .. c*64+63, stride 2064B
    const half_t* WB = g_WhS_hi + (size_t)(c * 64) * HID;
#pragma unroll
    for (int j = 0; j < 32; j++){
        int u = tid + j * 256;
        int row = u >> 7, q = u & 127;
        *(uint4*)(sm + S_WH + row*2064 + q*16) = *((const uint4*)(WB + (size_t)row*HID) + q);
    }

    uint32_t sbase = smem_u32(sm);
    uint32_t aA = sbase + S_A + (uint32_t)(l & 15) * 2064 + (l >> 4) * 16 + kg * 512;
    const int grp8 = l >> 3;
    const int n_off = (grp8 >> 1) * 8 + (l & 7);
    const int kblk = grp8 & 1;
    uint32_t aB = sbase + S_WH + (uint32_t)(wn*32 + n_off) * 2064 + kblk * 16 + kg * 512;
    __syncthreads();

    // ---- hoist this warp's Wh fragments into registers (persist all steps) ----
    uint32_t bf[16][8];
#pragma unroll
    for (int kk = 0; kk < 16; kk++){
        ldsm4(&bf[kk][0], aB + kk*32);
        ldsm4(&bf[kk][4], aB + 16*2064 + kk*32);
    }

    // hoisted epilogue constants; cell state in registers
    int ep_b[2], ep_jj[2]; float bhv[2][4]; float creg[2] = {0.f, 0.f};
#pragma unroll
    for (int e = 0; e < 2; e++){
        int p = tid + e * 256;
        ep_b[e] = p >> 4; ep_jj[e] = p & 15;
        int jb = c * 16 + ep_jj[e];
#pragma unroll
        for (int g = 0; g < 4; g++) bhv[e][g] = bh[g * HID + jb];
    }
    unsigned int* cnt = &g_cnt2[grp * 32];

    // gx prefetch for step 0
    float gxr[2][4];
    {
        const float* gxs = g_gx + (size_t)(grp * 32) * G4;
#pragma unroll
        for (int e = 0; e < 2; e++)
#pragma unroll
            for (int g = 0; g < 4; g++)
                gxr[e][g] = __ldcg(gxs + (size_t)ep_b[e] * G4 + g * HID + c * 16 + ep_jj[e]);
    }

    for (int s = 0; s < SQ; s++){
        const int sel = s & 1;
        const half_t* hh = g_h[sel]     + (size_t)grp * 32 * HID;
        half_t*      nhh = g_h[sel ^ 1] + (size_t)grp * 32 * HID;

        // ---- issue all h loads (full K, 16 cp16 per thread) ----
#pragma unroll
        for (int e = 0; e < 16; e++){
            int idx = tid + e * 256;
            int row = idx >> 7, q = idx & 127;
            cp16(sbase + S_A + row*2064 + q*16, hh + (size_t)row*HID + q*8);
        }
        CP_COMMIT();

        float d[2][4][4];
#pragma unroll
        for (int mf = 0; mf < 2; mf++)
#pragma unroll
            for (int nf = 0; nf < 4; nf++)
#pragma unroll
                for (int e = 0; e < 4; e++) d[mf][nf][e] = 0.f;

        CP_WAIT(0);
        __syncthreads();

        // ---- mainloop: 16 kk, A from smem, B from registers ----
#pragma unroll
        for (int kk = 0; kk < 16; kk++){
            uint32_t a0[4], a1[4];
            ldsm4(a0, aA + kk*32);
            ldsm4(a1, aA + 16*2064 + kk*32);
            mma_f16(d[0][0], a0, &bf[kk][0]); mma_f16(d[0][1], a0, &bf[kk][2]);
            mma_f16(d[0][2], a0, &bf[kk][4]); mma_f16(d[0][3], a0, &bf[kk][6]);
            mma_f16(d[1][0], a1, &bf[kk][0]); mma_f16(d[1][1], a1, &bf[kk][2]);
            mma_f16(d[1][2], a1, &bf[kk][4]); mma_f16(d[1][3], a1, &bf[kk][6]);
        }

        // ---- store partials (33-float padded rows) ----
        float* P = (float*)(sm + S_PT + wid * 4224);
#pragma unroll
        for (int mf = 0; mf < 2; mf++)
#pragma unroll
            for (int nf = 0; nf < 4; nf++){
                int r = mf*16 + (l >> 2), cc = nf*8 + (l & 3)*2;
                P[r*33 + cc]         = d[mf][nf][0];
                P[r*33 + cc + 1]     = d[mf][nf][1];
                P[(r+8)*33 + cc]     = d[mf][nf][2];
                P[(r+8)*33 + cc + 1] = d[mf][nf][3];
            }
        __syncthreads();

        // ---- fused reduce + cell update: 2 (b,jj) pairs per thread ----
#pragma unroll
        for (int e = 0; e < 2; e++){
            int b = ep_b[e], jj = ep_jj[e];
            float gv[4];
#pragma unroll
            for (int g = 0; g < 4; g++){
                int cc = g*16 + jj;
                int wnn = cc >> 5, ccl = cc & 31;
                float sum = 0.f;
#pragma unroll
                for (int k4 = 0; k4 < 4; k4++)
                    sum += ((const float*)(sm + S_PT + wnn*4224 + k4*8448))[b*33 + ccl];
                gv[g] = sum + gxr[e][g] + bhv[e][g];
            }
            float gi = fsigmoid(gv[0]);
            float gf = fsigmoid(gv[1]);
            float gg = ftanh(gv[2]);
            float go = fsigmoid(gv[3]);
            float cn = gf * creg[e] + gi * gg;
            creg[e] = cn;
            float hn = go * ftanh(cn);
            half_t h16 = __float2half_rn(hn);
            int j = c * 16 + jj;
            nhh[b*HID + j] = h16;
            g_hs[((size_t)(grp*32 + b) * SQ + s) * HID + j] = h16;
        }
        __syncthreads();     // all h writes done before arrive (race fix)

        // ---- prefetch next step's gx during barrier wait ----
        {
            int sn = (s + 1 < SQ) ? s + 1 : s;
            const float* gxs = g_gx + (size_t)(sn * NB + grp * 32) * G4;
#pragma unroll
            for (int e = 0; e < 2; e++)
#pragma unroll
                for (int g = 0; g < 4; g++)
                    gxr[e][g] = __ldcg(gxs + (size_t)ep_b[e] * G4 + g * HID + c * 16 + ep_jj[e]);
        }

        // ---- group barrier: release-atomic counter + single acquire-poller ----
        if (tid == 0){
            unsigned int dummy;
            asm volatile("atom.add.release.gpu.global.u32 %0, [%1], 1;"
                         : "=r"(dummy) : "l"(cnt) : "memory");
            unsigned int target = 64u * (unsigned int)(s + 1);
            unsigned int v;
            do {
                asm volatile("ld.acquire.gpu.global.u32 %0, [%1];"
                             : "=r"(v) : "l"(cnt) : "memory");
            } while (v < target);
        }
        __syncthreads();
    }
}

// ---------------------------------------------------------------------------
extern "C" void kernel_launch(void* const* d_in, const int* in_sizes, int n_in,
                              void* d_out, int out_size){
    const float* embed = (const float*)d_in[0];
    const float* Wi    = (const float*)d_in[1];
    const float* Wh    = (const float*)d_in[2];
    const float* bh    = (const float*)d_in[3];
    const float* Wo    = (const float*)d_in[4];
    const float* bo    = (const float*)d_in[5];
    const int*   x     = (const int*)d_in[6];
    float* out = (float*)d_out;

    const int TOT = NB * SQ;
    int logits_off = 0;
    if (out_size == TOT * (NA + 2)) logits_off = TOT;   // [dummy | logits | dummy]

    cudaFuncSetAttribute(gemm_gx1,  cudaFuncAttributeMaxDynamicSharedMemorySize, XSM_TOT);
    cudaFuncSetAttribute(lstm_scan, cudaFuncAttributeMaxDynamicSharedMemorySize, S_TOT);

    float *gx_p;
    cudaGetSymbolAddress((void**)&gx_p, g_gx);
    half_t *xe, *wih, *woh, *hs;
    cudaGetSymbolAddress((void**)&xe,  g_xe);
    cudaGetSymbolAddress((void**)&wih, g_WiT_hi);
    cudaGetSymbolAddress((void**)&woh, g_WoT_hi);
    cudaGetSymbolAddress((void**)&hs,  g_hs);

    // #0: Wi+Wh transpose/split (also zeroes h0 + barrier counters)
    trans_WiWh<<<dim3(32, 128, 2), dim3(32, 8)>>>(Wi, Wh);

    // #1: embedding gather
    gather_xe<<<MTOT, 128>>>(embed, x);

    // #2: gx = xe @ WiT^T  [32768 x 4096], 1-term fp16
    gemm_gx1<<<dim3(G4/128, MTOT/128), 256, XSM_TOT>>>(xe, wih, nullptr, gx_p, G4);

    // #3: persistent recurrent scan  (ncu captures this launch index)
    lstm_scan<<<128, 256, S_TOT>>>(bh);

    // #4: Wo transpose/split + zero output (dummies)
    trans_Wo_zero<<<dim3(32, 4), dim3(32, 8)>>>(Wo, out, out_size);

    // #5: logits = hs @ WoT^T + bo  [32768 x 128], 1-term fp16
    gemm_gx1<<<dim3(NA/128, MTOT/128), 256, XSM_TOT>>>(hs, woh, bo, out + logits_off, NA);
}

// round 16
// speedup vs baseline: 1.0397x; 1.0397x over previous
#include <cuda_runtime.h>
#include <cuda_fp16.h>
#include <math.h>
#include <stdint.h>

#define HID 1024
#define G4  4096
#define NB  64
#define SQ  512
#define NA  128
#define MTOT (NB*SQ)

typedef __half half_t;

// ---------------- device globals (allocation-free rule) ----------------
__device__ float g_gx[(size_t)SQ*NB*G4];                  // [S][B][4H] fp32
__device__ half_t g_xe[(size_t)MTOT*HID];                 // activations: single fp16
__device__ half_t g_WiT_hi[(size_t)G4*HID];               // weights: fp16 hi/lo
__device__ half_t g_WiT_lo[(size_t)G4*HID];
__device__ half_t g_WhS_hi[(size_t)G4*HID];               // scan-permuted rows (hi used)
__device__ half_t g_WhS_lo[(size_t)G4*HID];
__device__ half_t g_WoT_hi[(size_t)NA*HID];
__device__ half_t g_WoT_lo[(size_t)NA*HID];
__device__ half_t g_hs[(size_t)MTOT*HID];                 // [b*SQ+s][j]
__device__ half_t g_h[2][NB*HID];
__device__ unsigned int g_cnt2[64];                       // per-group barrier counters

// ---------------- helpers ----------------
static __device__ __forceinline__ uint32_t smem_u32(const void* p){
    uint32_t a;
    asm("{ .reg .u64 t; cvta.to.shared.u64 t, %1; cvt.u32.u64 %0, t; }" : "=r"(a) : "l"(p));
    return a;
}
static __device__ __forceinline__ void ldsm4(uint32_t* r, uint32_t a){
    asm volatile("ldmatrix.sync.aligned.m8n8.x4.shared.b16 {%0,%1,%2,%3}, [%4];"
        : "=r"(r[0]),"=r"(r[1]),"=r"(r[2]),"=r"(r[3]) : "r"(a));
}
static __device__ __forceinline__ void mma_f16(float* d, const uint32_t* a, const uint32_t* b){
    asm volatile("mma.sync.aligned.m16n8k16.row.col.f32.f16.f16.f32 "
        "{%0,%1,%2,%3}, {%4,%5,%6,%7}, {%8,%9}, {%0,%1,%2,%3};"
        : "+f"(d[0]),"+f"(d[1]),"+f"(d[2]),"+f"(d[3])
        : "r"(a[0]),"r"(a[1]),"r"(a[2]),"r"(a[3]), "r"(b[0]),"r"(b[1]));
}
static __device__ __forceinline__ void cp16(uint32_t dst, const void* src){
    asm volatile("cp.async.cg.shared.global [%0], [%1], 16;" :: "r"(dst), "l"(src));
}
#define CP_COMMIT() asm volatile("cp.async.commit_group;" ::: "memory")
#define CP_WAIT(n)  asm volatile("cp.async.wait_group %0;" :: "n"(n) : "memory")

static __device__ __forceinline__ void split_f16(float v, half_t& hi, half_t& lo){
    hi = __float2half_rn(v);
    lo = __float2half_rn(v - __half2float(hi));
}
static __device__ __forceinline__ float fsigmoid(float x){
    return 1.f / (1.f + __expf(-x));
}
static __device__ __forceinline__ float ftanh(float x){
    return 1.f - 2.f / (__expf(2.f * x) + 1.f);
}

// ---------------- prep kernels ----------------
// Combined Wi+Wh transpose/split (z=0: Wi plain; z=1: Wh permuted).
// Blocks with z==0 && y==0 additionally zero h0; block (0,0,0) zeroes cnt.
__global__ void trans_WiWh(const float* __restrict__ Wi, const float* __restrict__ Wh){
    __shared__ float tile[32][33];
    const int z = blockIdx.z;
    const float* W = z ? Wh : Wi;
    int k0 = blockIdx.x * 32, n0 = blockIdx.y * 32;
    int tx = threadIdx.x, ty = threadIdx.y;     // 32 x 8
    int tid = ty * 32 + tx;

    if (z == 0 && blockIdx.y == 0){
        uint32_t* hz = (uint32_t*)g_h;          // 2*NB*HID halves = 65536 u32
        int nthr = 32 * 256;
        for (int p = blockIdx.x * 256 + tid; p < 65536; p += nthr) hz[p] = 0u;
        if (blockIdx.x == 0 && tid < 64) g_cnt2[tid] = 0u;
    }

    for (int i = ty; i < 32; i += 8)
        tile[i][tx] = W[(size_t)(k0 + i) * G4 + n0 + tx];
    __syncthreads();
    for (int i = ty; i < 32; i += 8){
        int n = n0 + i, k = k0 + tx;
        float v = tile[tx][i];
        half_t hi, lo; split_f16(v, hi, lo);
        if (z){
            int r = ((n & 1023) >> 4) * 64 + (n >> 10) * 16 + (n & 15);
            g_WhS_hi[(size_t)r * HID + k] = hi;
            g_WhS_lo[(size_t)r * HID + k] = lo;
        } else {
            g_WiT_hi[(size_t)n * HID + k] = hi;
            g_WiT_lo[(size_t)n * HID + k] = lo;
        }
    }
}

__global__ void gather_xe(const float* __restrict__ embed, const int* __restrict__ x){
    int r = blockIdx.x;                 // 0..32767, r = s*64 + b
    int s = r >> 6, b = r & 63;
    int tok = x[b * SQ + s];
    const float* src = embed + (size_t)tok * HID;
    for (int k = threadIdx.x; k < HID; k += blockDim.x)
        g_xe[(size_t)r * HID + k] = __float2half_rn(src[k]);
}

// Wo transpose/split + zero entire output buffer (dummy regions stay zero)
__global__ void trans_Wo_zero(const float* __restrict__ W, float* out, int out_n){
    __shared__ float tile[32][33];
    int k0 = blockIdx.x * 32, n0 = blockIdx.y * 32;
    int tx = threadIdx.x, ty = threadIdx.y;
    int tid = ty * 32 + tx;
    int nthr = gridDim.x * gridDim.y * 256;
    int bid = blockIdx.y * gridDim.x + blockIdx.x;
    for (int p = bid * 256 + tid; p < out_n; p += nthr) out[p] = 0.f;

    for (int i = ty; i < 32; i += 8)
        tile[i][tx] = W[(size_t)(k0 + i) * NA + n0 + tx];
    __syncthreads();
    for (int i = ty; i < 32; i += 8){
        int n = n0 + i, k = k0 + tx;
        half_t hi, lo; split_f16(tile[tx][i], hi, lo);
        g_WoT_hi[(size_t)n * HID + k] = hi;
        g_WoT_lo[(size_t)n * HID + k] = lo;
    }
}

// ---------------- 1-term fp16 GEMM: 128x128 tile, 3-stage cp.async ----------------
#define X_AO   0
#define X_BO   18432
#define XBUF   36864
#define XSM_TOT (3*XBUF)

__global__ __launch_bounds__(256) void gemm_gx1(
    const half_t* __restrict__ A, const half_t* __restrict__ B,
    const float* __restrict__ bias, float* __restrict__ C, int ldc)
{
    extern __shared__ char sm[];
    const int tid = threadIdx.x, wid = tid >> 5, l = tid & 31;
    const int n0 = blockIdx.x * 128, m0 = blockIdx.y * 128;
    const int wm0 = (wid & 3) * 32, wn0 = (wid >> 2) * 64;

    uint32_t sbase = smem_u32(sm);

    uint32_t aA = sbase + X_AO + (uint32_t)(wm0 + (l & 15)) * 144 + (l >> 4) * 16;
    const int grp8 = l >> 3;
    const int n_off = (grp8 >> 1) * 8 + (l & 7);
    const int kblk = grp8 & 1;
    uint32_t aB = sbase + X_BO + (uint32_t)(wn0 + n_off) * 144 + kblk * 16;

    float d[2][8][4];
#pragma unroll
    for (int m = 0; m < 2; m++)
#pragma unroll
        for (int q = 0; q < 8; q++)
#pragma unroll
            for (int e = 0; e < 4; e++) d[m][q][e] = 0.f;

    auto issue = [&](int c, int buf){
        const int k0 = c * 64;
        uint32_t bb = sbase + buf * XBUF;
#pragma unroll
        for (int e = 0; e < 4; e++){
            int idx = tid + e * 256;
            int row = idx >> 3, q = idx & 7;
            cp16(bb + X_AO + row*144 + q*16, A + (size_t)(m0 + row)*HID + k0 + q*8);
            cp16(bb + X_BO + row*144 + q*16, B + (size_t)(n0 + row)*HID + k0 + q*8);
        }
    };

    issue(0, 0); CP_COMMIT();
    issue(1, 1); CP_COMMIT();

    for (int c = 0; c < 16; c++){
        if (c < 14){ issue(c + 2, (c + 2) % 3); CP_COMMIT(); CP_WAIT(2); }
        else if (c == 14){ CP_WAIT(1); }
        else { CP_WAIT(0); }
        __syncthreads();
        const uint32_t bo = (uint32_t)(c % 3) * XBUF;
#pragma unroll
        for (int ks = 0; ks < 4; ks++){
            uint32_t ah[2][4];
            ldsm4(ah[0], aA + bo + ks*32);
            ldsm4(ah[1], aA + bo + 16*144 + ks*32);
            uint32_t bb4[4][4];
#pragma unroll
            for (int g = 0; g < 4; g++)
                ldsm4(bb4[g], aB + bo + g*2304 + ks*32);
#pragma unroll
            for (int m = 0; m < 2; m++)
#pragma unroll
                for (int g = 0; g < 4; g++)
#pragma unroll
                    for (int nn = 0; nn < 2; nn++)
                        mma_f16(d[m][g*2+nn], ah[m], bb4[g] + nn*2);
        }
        __syncthreads();
    }

#pragma unroll
    for (int m = 0; m < 2; m++)
#pragma unroll
        for (int q = 0; q < 8; q++){
            int row0 = m0 + wm0 + m*16 + (l >> 2);
            int col  = n0 + wn0 + q*8 + (l & 3)*2;
            float2 v0 = make_float2(d[m][q][0], d[m][q][1]);
            float2 v1 = make_float2(d[m][q][2], d[m][q][3]);
            if (bias){
                float b0 = bias[col], b1 = bias[col+1];
                v0.x += b0; v0.y += b1; v1.x += b0; v1.y += b1;
            }
            *(float2*)(C + (size_t)row0*ldc + col)     = v0;
            *(float2*)(C + (size_t)(row0+8)*ldc + col) = v1;
        }
}

// ---------------- persistent LSTM scan: 512 threads, 16 warps ----------------
// 2 batch groups x 64 column-CTAs. CTA (grp,c): batch rows grp*32..+31,
// hidden units c*16..+15 (64 gate cols). 16 warps = 4 wn (n16=1 gate) x 4 kg (k256).
// Wh fragments ldsm'd ONCE into 64 regs/thread; staging smem region reused
// for fp32 partials. Same 4-way K-split as before -> bit-identical gate sums.
#define S_PT   0                 // 16 partials x 4224 = 67584 (overlaps Wh staging)
#define S_A    132096            // 32 rows x 2064B = 66048 (full K)
#define S_TOT  198144

__global__ __launch_bounds__(512, 1) void lstm_scan(const float* __restrict__ bh){
    extern __shared__ char sm[];
    const int tid = threadIdx.x, wid = tid >> 5, l = tid & 31;
    const int cta = blockIdx.x;
    const int grp = cta >> 6;          // batch group 0/1
    const int c   = cta & 63;          // column slice
    const int wn  = wid & 3;           // gate (16 cols each)
    const int kg  = wid >> 2;          // k-chunk (256)

    // stage Wh slice (rows c*64..+63, stride 2064B) at offset 0 (temporary)
    const half_t* WB = g_WhS_hi + (size_t)(c * 64) * HID;
#pragma unroll
    for (int j = 0; j < 16; j++){
        int u = tid + j * 512;
        int row = u >> 7, q = u & 127;
        *(uint4*)(sm + row*2064 + q*16) = *((const uint4*)(WB + (size_t)row*HID) + q);
    }
    __syncthreads();

    uint32_t sbase = smem_u32(sm);
    uint32_t aA = sbase + S_A + (uint32_t)(l & 15) * 2064 + (l >> 4) * 16 + kg * 512;
    const int grp8 = l >> 3;
    const int n_off = (grp8 >> 1) * 8 + (l & 7);
    const int kblk = grp8 & 1;
    uint32_t aB = sbase + (uint32_t)(wn*16 + n_off) * 2064 + kblk * 16 + kg * 512;

    // hoist this warp's Wh fragments (n16 x k256) into 64 registers
    uint32_t bf[16][4];
#pragma unroll
    for (int kk = 0; kk < 16; kk++)
        ldsm4(bf[kk], aB + kk*32);
    __syncthreads();               // staging region now reusable as partials

    // epilogue constants: exactly one (b,jj) pair per thread
    const int b  = tid >> 4;       // 0..31
    const int jj = tid & 15;
    const int jb = c * 16 + jj;
    float bhv[4];
#pragma unroll
    for (int g = 0; g < 4; g++) bhv[g] = bh[g * HID + jb];
    float creg = 0.f;
    unsigned int* cnt = &g_cnt2[grp * 32];

    for (int s = 0; s < SQ; s++){
        const int sel = s & 1;
        const half_t* hh = g_h[sel]     + (size_t)grp * 32 * HID;
        half_t*      nhh = g_h[sel ^ 1] + (size_t)grp * 32 * HID;

        // ---- issue all h loads (full K, 8 cp16 per thread) ----
#pragma unroll
        for (int e = 0; e < 8; e++){
            int idx = tid + e * 512;
            int row = idx >> 7, q = idx & 127;
            cp16(sbase + S_A + row*2064 + q*16, hh + (size_t)row*HID + q*8);
        }
        CP_COMMIT();

        // ---- gx for this step straight into registers ----
        const float* gxs = g_gx + (size_t)(s * NB + grp * 32) * G4;
        float gxr[4];
#pragma unroll
        for (int g = 0; g < 4; g++)
            gxr[g] = __ldcg(gxs + (size_t)b * G4 + g * HID + jb);

        float d[2][2][4];
#pragma unroll
        for (int mf = 0; mf < 2; mf++)
#pragma unroll
            for (int nf = 0; nf < 2; nf++)
#pragma unroll
                for (int e = 0; e < 4; e++) d[mf][nf][e] = 0.f;

        CP_WAIT(0);
        __syncthreads();

        // ---- mainloop: 16 kk, A from smem, B from registers ----
#pragma unroll
        for (int kk = 0; kk < 16; kk++){
            uint32_t a0[4], a1[4];
            ldsm4(a0, aA + kk*32);
            ldsm4(a1, aA + 16*2064 + kk*32);
            mma_f16(d[0][0], a0, &bf[kk][0]); mma_f16(d[0][1], a0, &bf[kk][2]);
            mma_f16(d[1][0], a1, &bf[kk][0]); mma_f16(d[1][1], a1, &bf[kk][2]);
        }

        // ---- store partials (33-float padded rows, 4224B/warp) ----
        float* P = (float*)(sm + S_PT + wid * 4224);
#pragma unroll
        for (int mf = 0; mf < 2; mf++)
#pragma unroll
            for (int nf = 0; nf < 2; nf++){
                int r = mf*16 + (l >> 2), cc = nf*8 + (l & 3)*2;
                P[r*33 + cc]         = d[mf][nf][0];
                P[r*33 + cc + 1]     = d[mf][nf][1];
                P[(r+8)*33 + cc]     = d[mf][nf][2];
                P[(r+8)*33 + cc + 1] = d[mf][nf][3];
            }
        __syncthreads();

        // ---- fused reduce + cell update: 1 (b,jj) pair per thread ----
        float gv[4];
#pragma unroll
        for (int g = 0; g < 4; g++){
            float sum = 0.f;
#pragma unroll
            for (int k4 = 0; k4 < 4; k4++)
                sum += ((const float*)(sm + S_PT + (k4*4 + g)*4224))[b*33 + jj];
            gv[g] = sum + gxr[g] + bhv[g];
        }
        float gi = fsigmoid(gv[0]);
        float gf = fsigmoid(gv[1]);
        float gg = ftanh(gv[2]);
        float go = fsigmoid(gv[3]);
        float cn = gf * creg + gi * gg;
        creg = cn;
        float hn = go * ftanh(cn);
        half_t h16 = __float2half_rn(hn);
        nhh[b*HID + jb] = h16;
        g_hs[((size_t)(grp*32 + b) * SQ + s) * HID + jb] = h16;
        __syncthreads();     // all h writes done before arrive

        // ---- group barrier: release-atomic counter + single acquire-poller ----
        if (tid == 0){
            unsigned int dummy;
            asm volatile("atom.add.release.gpu.global.u32 %0, [%1], 1;"
                         : "=r"(dummy) : "l"(cnt) : "memory");
            unsigned int target = 64u * (unsigned int)(s + 1);
            unsigned int v;
            do {
                asm volatile("ld.acquire.gpu.global.u32 %0, [%1];"
                             : "=r"(v) : "l"(cnt) : "memory");
            } while (v < target);
        }
        __syncthreads();
    }
}

// ---------------------------------------------------------------------------
extern "C" void kernel_launch(void* const* d_in, const int* in_sizes, int n_in,
                              void* d_out, int out_size){
    const float* embed = (const float*)d_in[0];
    const float* Wi    = (const float*)d_in[1];
    const float* Wh    = (const float*)d_in[2];
    const float* bh    = (const float*)d_in[3];
    const float* Wo    = (const float*)d_in[4];
    const float* bo    = (const float*)d_in[5];
    const int*   x     = (const int*)d_in[6];
    float* out = (float*)d_out;

    const int TOT = NB * SQ;
    int logits_off = 0;
    if (out_size == TOT * (NA + 2)) logits_off = TOT;   // [dummy | logits | dummy]

    cudaFuncSetAttribute(gemm_gx1,  cudaFuncAttributeMaxDynamicSharedMemorySize, XSM_TOT);
    cudaFuncSetAttribute(lstm_scan, cudaFuncAttributeMaxDynamicSharedMemorySize, S_TOT);

    float *gx_p;
    cudaGetSymbolAddress((void**)&gx_p, g_gx);
    half_t *xe, *wih, *woh, *hs;
    cudaGetSymbolAddress((void**)&xe,  g_xe);
    cudaGetSymbolAddress((void**)&wih, g_WiT_hi);
    cudaGetSymbolAddress((void**)&woh, g_WoT_hi);
    cudaGetSymbolAddress((void**)&hs,  g_hs);

    // #0: Wi+Wh transpose/split (also zeroes h0 + barrier counters)
    trans_WiWh<<<dim3(32, 128, 2), dim3(32, 8)>>>(Wi, Wh);

    // #1: embedding gather
    gather_xe<<<MTOT, 128>>>(embed, x);

    // #2: gx = xe @ WiT^T  [32768 x 4096], 1-term fp16, 3-stage
    gemm_gx1<<<dim3(G4/128, MTOT/128), 256, XSM_TOT>>>(xe, wih, nullptr, gx_p, G4);

    // #3: persistent recurrent scan (512 threads; ncu captures this index)
    lstm_scan<<<128, 512, S_TOT>>>(bh);

    // #4: Wo transpose/split + zero output (dummies)
    trans_Wo_zero<<<dim3(32, 4), dim3(32, 8)>>>(Wo, out, out_size);

    // #5: logits = hs @ WoT^T + bo  [32768 x 128], 1-term fp16, 3-stage
    gemm_gx1<<<dim3(NA/128, MTOT/128), 256, XSM_TOT>>>(hs, woh, bo, out + logits_off, NA);
}